// round 2
// baseline (speedup 1.0000x reference)
#include <cuda_runtime.h>
#include <cuda_bf16.h>

// ---------------------------------------------------------------------------
// RPN training loss (faithful port of the buggy reference):
//   gt_idx[i] = argmax_j IoU(anchor_i, gt_j)   (first-max wins ties)
//   label = 1 if gt_idx >= 1, 0 if gt_idx == 0
//   sel   = first min(num_pos,128) positives by anchor index, then negatives
//           by anchor index (spilling back into positives if negatives run out)
//   cls   = mean softmax-CE over 256 samples
//   reg   = mean over 256 of 2 * sum smoothL1(label * (pred - encode))
//
// K1: argmax via division-free exact-rational compare (inter*bestU > bestI*uni)
//     + per-32-anchor-group pos/neg counts (warp ballot).
// K2: ONE block: scan group counts -> offsets/totals, warp-parallel select of
//     first 256 pos/neg anchors, then the 256-sample loss. No extra launches.
// ---------------------------------------------------------------------------

#define NMAX   (1 << 20)
#define NGMAX  (NMAX / 32)      // 32768 groups of 32 anchors
#define MMAX   512
#define CAP    256

__device__ int g_gt_idx[NMAX];
__device__ int g_grp_pos[NGMAX];
__device__ int g_grp_neg[NGMAX];
__device__ int g_po[NGMAX];     // exclusive pos offsets per group
__device__ int g_no[NGMAX];     // exclusive neg offsets per group

// --------------------------------------------------------------------------
// K1: per-anchor argmax IoU. Division-free: maintain best as a rational
// (bestI / bestU); update when inter*bestU > bestI*uni. Exact unless two IoUs
// agree to ~1 ulp (strict '>' keeps the first max, matching jnp.argmax).
// --------------------------------------------------------------------------
__global__ void k_argmax(const float4* __restrict__ anchors,
                         const float4* __restrict__ gt,
                         int N, int M) {
    __shared__ float4 sg[MMAX];
    __shared__ float  sga[MMAX];
    for (int j = threadIdx.x; j < M; j += blockDim.x) {
        float4 g = gt[j];
        sg[j]  = g;
        sga[j] = (g.z - g.x) * (g.w - g.y);
    }
    __syncthreads();

    int i = blockIdx.x * blockDim.x + threadIdx.x;
    int best = 0;
    if (i < N) {
        float4 a = anchors[i];
        float areaA = (a.z - a.x) * (a.w - a.y);
        float bestI = 0.0f;   // intersection of current best
        float bestU = 1.0f;   // union of current best (dummy 1 so 0/1 = 0)
        #pragma unroll 4
        for (int j = 0; j < M; ++j) {
            float4 g = sg[j];
            float w = fminf(a.z, g.z) - fmaxf(a.x, g.x);
            float h = fminf(a.w, g.w) - fmaxf(a.y, g.y);
            w = fmaxf(w, 0.0f);
            h = fmaxf(h, 0.0f);
            float inter = w * h;
            float uni = (areaA + sga[j]) - inter;
            bool upd = inter * bestU > bestI * uni;
            bestI = upd ? inter : bestI;
            bestU = upd ? uni   : bestU;
            best  = upd ? j     : best;
        }
        g_gt_idx[i] = best;
    }

    int is_pos = (i < N) && (best >= 1);
    int is_neg = (i < N) && (best == 0);
    unsigned bp = __ballot_sync(0xffffffffu, is_pos);
    unsigned bn = __ballot_sync(0xffffffffu, is_neg);
    if ((threadIdx.x & 31) == 0) {
        int grp = blockIdx.x * (blockDim.x >> 5) + (threadIdx.x >> 5);
        g_grp_pos[grp] = __popc(bp);
        g_grp_neg[grp] = __popc(bn);
    }
}

// --------------------------------------------------------------------------
// K2: single block, 256 threads. Scan -> select -> loss.
// --------------------------------------------------------------------------
__global__ void k_finish(const float2* __restrict__ score,
                         const float4* __restrict__ pred,
                         const float4* __restrict__ anchors,
                         const float4* __restrict__ gt,
                         float* __restrict__ out,
                         int N, int ng) {
    __shared__ int sp[256], sn[256];
    __shared__ int s_pos[CAP], s_neg[CAP];
    __shared__ int s_nproc, s_num_pos, s_num_neg;
    __shared__ float rc[256], rr[256];

    int t = threadIdx.x;
    if (t == 0) s_nproc = 1;
    s_pos[t] = 0;
    s_neg[t] = 0;

    // ---- phase 1: scan group counts -> exclusive offsets (to global) ----
    int per = (ng + 255) / 256;
    int base = t * per;
    int lim = min(base + per, ng);
    int sump = 0, sumn = 0;
    for (int k = base; k < lim; ++k) { sump += g_grp_pos[k]; sumn += g_grp_neg[k]; }
    sp[t] = sump; sn[t] = sumn;
    __syncthreads();
    for (int off = 1; off < 256; off <<= 1) {
        int vp = (t >= off) ? sp[t - off] : 0;
        int vn = (t >= off) ? sn[t - off] : 0;
        __syncthreads();
        sp[t] += vp; sn[t] += vn;
        __syncthreads();
    }
    int rp = (t == 0) ? 0 : sp[t - 1];
    int rn = (t == 0) ? 0 : sn[t - 1];
    int need_max = -1;
    for (int k = base; k < lim; ++k) {
        g_po[k] = rp;
        g_no[k] = rn;
        if (rp < CAP || rn < CAP) need_max = k;
        rp += g_grp_pos[k];
        rn += g_grp_neg[k];
    }
    if (need_max >= 0) atomicMax(&s_nproc, need_max + 1);
    if (t == 255) { s_num_pos = sp[255]; s_num_neg = sn[255]; }
    __syncthreads();   // offsets visible (global+shared) to whole block

    // ---- phase 2: warp-parallel select of first CAP pos / neg anchors ----
    {
        int lane = t & 31;
        int w = t >> 5;
        unsigned ltmask = (1u << lane) - 1u;
        int nproc = s_nproc;
        for (int g = w; g < nproc; g += 8) {
            int idx = g * 32 + lane;
            int gi = (idx < N) ? g_gt_idx[idx] : -1;
            int is_pos = (gi >= 1);
            int is_neg = (gi == 0);
            unsigned bp = __ballot_sync(0xffffffffu, is_pos);
            unsigned bn = __ballot_sync(0xffffffffu, is_neg);
            if (is_pos) {
                int r = g_po[g] + __popc(bp & ltmask);
                if (r < CAP) s_pos[r] = idx;
            }
            if (is_neg) {
                int r = g_no[g] + __popc(bn & ltmask);
                if (r < CAP) s_neg[r] = idx;
            }
        }
    }
    __syncthreads();

    // ---- phase 3: 256-sample loss ----
    int num_pos = s_num_pos;
    int num_neg = s_num_neg;
    int cur_pos = min(num_pos, 128);

    int a, label;
    if (t < cur_pos) {
        a = s_pos[t];
        label = 1;
    } else {
        int j = t - cur_pos;
        if (j < num_neg) {
            a = s_neg[min(j, CAP - 1)];
            label = 0;
        } else {
            // stable neg_order spills into positives in anchor-index order
            a = s_pos[min(j - num_neg, CAP - 1)];
            label = 1;
        }
    }

    // classification: -log_softmax(score[a])[label]
    float2 s = score[a];
    float m = fmaxf(s.x, s.y);
    float lse = m + logf(expf(s.x - m) + expf(s.y - m));
    float cls = lse - (label ? s.y : s.x);

    // regression: smooth-L1 on encoded target, zeroed for negatives
    float4 ab = anchors[a];
    int gi = g_gt_idx[a];
    float4 gb = gt[gi];
    float aw = ab.z - ab.x, ah = ab.w - ab.y;
    float acx = ab.x + 0.5f * aw, acy = ab.y + 0.5f * ah;
    float gw = gb.z - gb.x, gh = gb.w - gb.y;
    float gcx = gb.x + 0.5f * gw, gcy = gb.y + 0.5f * gh;
    float t0 = (gcx - acx) / aw;
    float t1 = (gcy - acy) / ah;
    float t2 = logf(gw / aw);
    float t3 = logf(gh / ah);
    float4 p = pred[a];
    float fl = (float)label;
    float d0 = fl * (p.x - t0);
    float d1 = fl * (p.y - t1);
    float d2 = fl * (p.z - t2);
    float d3 = fl * (p.w - t3);
    float ad0 = fabsf(d0), ad1 = fabsf(d1), ad2 = fabsf(d2), ad3 = fabsf(d3);
    float s0 = (ad0 < 1.0f) ? 0.5f * d0 * d0 : ad0 - 0.5f;
    float s1 = (ad1 < 1.0f) ? 0.5f * d1 * d1 : ad1 - 0.5f;
    float s2 = (ad2 < 1.0f) ? 0.5f * d2 * d2 : ad2 - 0.5f;
    float s3 = (ad3 < 1.0f) ? 0.5f * d3 * d3 : ad3 - 0.5f;
    float reg = 2.0f * (s0 + s1 + s2 + s3);

    rc[t] = cls;
    rr[t] = reg;
    __syncthreads();
    for (int off = 128; off > 0; off >>= 1) {
        if (t < off) { rc[t] += rc[t + off]; rr[t] += rr[t + off]; }
        __syncthreads();
    }
    if (t == 0) {
        out[0] = rc[0] * (1.0f / 256.0f);   // CLS_W = 1.0
        out[1] = rr[0] * (1.0f / 256.0f);
    }
}

extern "C" void kernel_launch(void* const* d_in, const int* in_sizes, int n_in,
                              void* d_out, int out_size) {
    const float2* score   = (const float2*)d_in[0];   // [N,2]
    const float4* pred    = (const float4*)d_in[1];   // [N,4]
    const float4* anchors = (const float4*)d_in[2];   // [N,4]
    const float4* gt      = (const float4*)d_in[3];   // [M,4]
    float* out = (float*)d_out;

    int N = in_sizes[2] / 4;
    int M = in_sizes[3] / 4;
    int nb = (N + 255) / 256;
    int ng = nb * 8;              // groups of 32 anchors (incl. padded tail)

    k_argmax<<<nb, 256>>>(anchors, gt, N, M);
    k_finish<<<1, 256>>>(score, pred, anchors, gt, out, N, ng);
}

// round 3
// speedup vs baseline: 2.8918x; 2.8918x over previous
#include <cuda_runtime.h>
#include <cuda_bf16.h>

// ---------------------------------------------------------------------------
// RPN training loss (faithful port of the buggy reference):
//   gt_idx[i] = argmax_j IoU(anchor_i, gt_j)   (first-max wins ties)
//   label = 1 if gt_idx >= 1, 0 if gt_idx == 0
//   sel   = first min(num_pos,128) positives by anchor index, then negatives
//           by anchor index (spilling back into positives if negatives run out)
//   cls   = mean softmax-CE over 256 samples
//   reg   = mean over 256 of 2 * sum smoothL1(label * (pred - encode))
//
// Insight: selection only depends on labels of the earliest anchors (until
// 128 positives AND 128 negatives are found), and gt_idx is only consumed for
// the <=256 selected anchors. So:
//   k_front: exact argmax for the first F=8192 anchors (+ block counts)
//   k_full : covers [F, N) but returns instantly if the front region already
//            contains >=128 pos and >=128 neg (general fallback otherwise)
//   k_tail : one block — scan gt_idx in order, collect first-256 pos/neg,
//            compute both losses.
// Argmax is division-free: best kept as rational (bestI/bestU), update when
// inter*bestU > bestI*uni (strict '>' => first-max wins, matching jnp.argmax).
// ---------------------------------------------------------------------------

#define NMAX     (1 << 20)
#define FBLK     64
#define FTHR     128
#define FRONT    (FBLK * FTHR)    // 8192
#define SMG      2048             // gt boxes cached in smem (M <= SMG)
#define CAP      256

__device__ int g_gt_idx[NMAX];
__device__ int g_fp[FBLK];
__device__ int g_fn[FBLK];

// ---- shared dense argmax body -------------------------------------------
__device__ __forceinline__ int argmax_iou(const float4 a,
                                          const float4* __restrict__ gtp,
                                          const float* __restrict__ areap,
                                          int M) {
    float areaA = (a.z - a.x) * (a.w - a.y);
    float bestI = 0.0f;   // intersection of current best
    float bestU = 1.0f;   // union of current best (dummy so 0/1 = 0)
    int best = 0;
    #pragma unroll 4
    for (int j = 0; j < M; ++j) {
        float4 g = gtp[j];
        float w = fminf(a.z, g.z) - fmaxf(a.x, g.x);
        float h = fminf(a.w, g.w) - fmaxf(a.y, g.y);
        w = fmaxf(w, 0.0f);
        h = fmaxf(h, 0.0f);
        float inter = w * h;
        float uni = (areaA + areap[j]) - inter;
        bool upd = inter * bestU > bestI * uni;
        bestI = upd ? inter : bestI;
        bestU = upd ? uni   : bestU;
        best  = upd ? j     : best;
    }
    return best;
}

// --------------------------------------------------------------------------
// K1: argmax for first FRONT anchors + per-block pos/neg counts.
// --------------------------------------------------------------------------
__global__ void k_front(const float4* __restrict__ anchors,
                        const float4* __restrict__ gt,
                        int N, int M) {
    __shared__ float4 sg[SMG];
    __shared__ float  sga[SMG];
    int Ms = min(M, SMG);
    for (int j = threadIdx.x; j < Ms; j += blockDim.x) {
        float4 g = gt[j];
        sg[j]  = g;
        sga[j] = (g.z - g.x) * (g.w - g.y);
    }
    __syncthreads();

    int i = blockIdx.x * FTHR + threadIdx.x;
    int best = 0;
    if (i < N) {
        if (M <= SMG) {
            best = argmax_iou(anchors[i], sg, sga, M);
        } else {
            // huge-M fallback: stream gt from global
            float4 a = anchors[i];
            float areaA = (a.z - a.x) * (a.w - a.y);
            float bestI = 0.0f, bestU = 1.0f;
            for (int j = 0; j < M; ++j) {
                float4 g = __ldg(&gt[j]);
                float areaB = (g.z - g.x) * (g.w - g.y);
                float w = fmaxf(fminf(a.z, g.z) - fmaxf(a.x, g.x), 0.0f);
                float h = fmaxf(fminf(a.w, g.w) - fmaxf(a.y, g.y), 0.0f);
                float inter = w * h;
                float uni = (areaA + areaB) - inter;
                bool upd = inter * bestU > bestI * uni;
                bestI = upd ? inter : bestI;
                bestU = upd ? uni : bestU;
                best = upd ? j : best;
            }
        }
        g_gt_idx[i] = best;
    }

    int is_pos = (i < N) && (best >= 1);
    int is_neg = (i < N) && (best == 0);
    int cp = __syncthreads_count(is_pos);
    int cn = __syncthreads_count(is_neg);
    if (threadIdx.x == 0) {
        g_fp[blockIdx.x] = cp;
        g_fn[blockIdx.x] = cn;
    }
}

// --------------------------------------------------------------------------
// K2: anchors [FRONT, N). Early-exit when the front region already decided
// the whole selection (>=128 pos and >=128 neg among first FRONT anchors).
// --------------------------------------------------------------------------
__global__ void k_full(const float4* __restrict__ anchors,
                       const float4* __restrict__ gt,
                       int N, int M) {
    __shared__ int s_ok;
    {
        int t = threadIdx.x;
        int vp = (t < FBLK) ? g_fp[t] : 0;
        int vn = (t < FBLK) ? g_fn[t] : 0;
        #pragma unroll
        for (int o = 16; o > 0; o >>= 1) {
            vp += __shfl_down_sync(0xffffffffu, vp, o);
            vn += __shfl_down_sync(0xffffffffu, vn, o);
        }
        __shared__ int sp2[2], sn2[2];
        if ((t & 31) == 0 && t < FBLK) { sp2[t >> 5] = vp; sn2[t >> 5] = vn; }
        __syncthreads();
        if (t == 0) s_ok = (sp2[0] + sp2[1] >= 128) && (sn2[0] + sn2[1] >= 128);
        __syncthreads();
    }
    if (s_ok) return;

    __shared__ float4 sg[SMG];
    __shared__ float  sga[SMG];
    int Ms = min(M, SMG);
    for (int j = threadIdx.x; j < Ms; j += blockDim.x) {
        float4 g = gt[j];
        sg[j]  = g;
        sga[j] = (g.z - g.x) * (g.w - g.y);
    }
    __syncthreads();

    int i = FRONT + blockIdx.x * blockDim.x + threadIdx.x;
    if (i >= N) return;
    int best;
    if (M <= SMG) {
        best = argmax_iou(anchors[i], sg, sga, M);
    } else {
        float4 a = anchors[i];
        float areaA = (a.z - a.x) * (a.w - a.y);
        float bestI = 0.0f, bestU = 1.0f;
        best = 0;
        for (int j = 0; j < M; ++j) {
            float4 g = __ldg(&gt[j]);
            float areaB = (g.z - g.x) * (g.w - g.y);
            float w = fmaxf(fminf(a.z, g.z) - fmaxf(a.x, g.x), 0.0f);
            float h = fmaxf(fminf(a.w, g.w) - fmaxf(a.y, g.y), 0.0f);
            float inter = w * h;
            float uni = (areaA + areaB) - inter;
            bool upd = inter * bestU > bestI * uni;
            bestI = upd ? inter : bestI;
            bestU = upd ? uni : bestU;
            best = upd ? j : best;
        }
    }
    g_gt_idx[i] = best;
}

// --------------------------------------------------------------------------
// K3: one block, 256 threads: ordered select of first-256 pos/neg + loss.
// --------------------------------------------------------------------------
__global__ void k_tail(const float2* __restrict__ score,
                       const float4* __restrict__ pred,
                       const float4* __restrict__ anchors,
                       const float4* __restrict__ gt,
                       float* __restrict__ out,
                       int N, int M) {
    __shared__ int s_pos[CAP], s_neg[CAP];
    __shared__ int wp[8], wn[8];
    __shared__ int s_cntp, s_cntn, s_limit;
    __shared__ float rc[256], rr[256];

    int t = threadIdx.x;
    int lane = t & 31;
    int warp = t >> 5;
    unsigned ltmask = (1u << lane) - 1u;

    s_pos[t] = 0;
    s_neg[t] = 0;

    // front sufficiency -> scan limit (never read unwritten gt_idx)
    {
        int vp = (t < FBLK) ? g_fp[t] : 0;
        int vn = (t < FBLK) ? g_fn[t] : 0;
        #pragma unroll
        for (int o = 16; o > 0; o >>= 1) {
            vp += __shfl_down_sync(0xffffffffu, vp, o);
            vn += __shfl_down_sync(0xffffffffu, vn, o);
        }
        if ((t & 31) == 0 && t < FBLK) { wp[warp] = vp; wn[warp] = vn; }
        __syncthreads();
        if (t == 0) {
            int fp = wp[0] + wp[1], fn = wn[0] + wn[1];
            s_limit = (fp >= 128 && fn >= 128) ? min(FRONT, N) : N;
            s_cntp = 0;
            s_cntn = 0;
        }
        __syncthreads();
    }
    int limit = s_limit;

    // ordered chunk scan, double-buffered loads
    int idx0 = t;
    int gi0 = (idx0 < limit) ? g_gt_idx[idx0] : -1;
    for (int base = 0; base < limit; base += 256) {
        int idx1 = base + 256 + t;
        int gi1 = (idx1 < limit) ? g_gt_idx[idx1] : -1;

        int cp0 = s_cntp, cn0 = s_cntn;
        int is_pos = (gi0 >= 1);
        int is_neg = (gi0 == 0);
        unsigned bp = __ballot_sync(0xffffffffu, is_pos);
        unsigned bn = __ballot_sync(0xffffffffu, is_neg);
        if (lane == 0) { wp[warp] = __popc(bp); wn[warp] = __popc(bn); }
        __syncthreads();
        int basep = 0, basen = 0;
        for (int w = 0; w < warp; ++w) { basep += wp[w]; basen += wn[w]; }
        if (is_pos) {
            int r = cp0 + basep + __popc(bp & ltmask);
            if (r < CAP) s_pos[r] = base + t;
        }
        if (is_neg) {
            int r = cn0 + basen + __popc(bn & ltmask);
            if (r < CAP) s_neg[r] = base + t;
        }
        if (t == 0) {
            int tp = 0, tn = 0;
            #pragma unroll
            for (int w = 0; w < 8; ++w) { tp += wp[w]; tn += wn[w]; }
            s_cntp = cp0 + tp;
            s_cntn = cn0 + tn;
        }
        __syncthreads();
        if (s_cntp >= CAP && s_cntn >= CAP) break;
        gi0 = gi1;
    }

    // sample mapping (cnt >= CAP means true count also >= CAP > 128, so
    // min()/spill logic below is exact in all cases)
    int num_pos = s_cntp;
    int num_neg = s_cntn;
    int cur_pos = min(num_pos, 128);

    int a, label;
    if (t < cur_pos) {
        a = s_pos[t];
        label = 1;
    } else {
        int j = t - cur_pos;
        if (j < num_neg) {
            a = s_neg[min(j, CAP - 1)];
            label = 0;
        } else {
            // stable neg_order spills into positives in anchor-index order
            a = s_pos[min(j - num_neg, CAP - 1)];
            label = 1;
        }
    }

    // classification: -log_softmax(score[a])[label]
    float2 s = score[a];
    float m = fmaxf(s.x, s.y);
    float lse = m + logf(expf(s.x - m) + expf(s.y - m));
    float cls = lse - (label ? s.y : s.x);

    // regression: smooth-L1 on encoded target, zeroed for negatives
    float4 ab = anchors[a];
    int gi = g_gt_idx[a];
    float4 gb = gt[gi];
    float aw = ab.z - ab.x, ah = ab.w - ab.y;
    float acx = ab.x + 0.5f * aw, acy = ab.y + 0.5f * ah;
    float gw = gb.z - gb.x, gh = gb.w - gb.y;
    float gcx = gb.x + 0.5f * gw, gcy = gb.y + 0.5f * gh;
    float t0 = (gcx - acx) / aw;
    float t1 = (gcy - acy) / ah;
    float t2 = logf(gw / aw);
    float t3 = logf(gh / ah);
    float4 p = pred[a];
    float fl = (float)label;
    float d0 = fl * (p.x - t0);
    float d1 = fl * (p.y - t1);
    float d2 = fl * (p.z - t2);
    float d3 = fl * (p.w - t3);
    float ad0 = fabsf(d0), ad1 = fabsf(d1), ad2 = fabsf(d2), ad3 = fabsf(d3);
    float s0 = (ad0 < 1.0f) ? 0.5f * d0 * d0 : ad0 - 0.5f;
    float s1 = (ad1 < 1.0f) ? 0.5f * d1 * d1 : ad1 - 0.5f;
    float s2 = (ad2 < 1.0f) ? 0.5f * d2 * d2 : ad2 - 0.5f;
    float s3 = (ad3 < 1.0f) ? 0.5f * d3 * d3 : ad3 - 0.5f;
    float reg = 2.0f * (s0 + s1 + s2 + s3);

    rc[t] = cls;
    rr[t] = reg;
    __syncthreads();
    for (int off = 128; off > 0; off >>= 1) {
        if (t < off) { rc[t] += rc[t + off]; rr[t] += rr[t + off]; }
        __syncthreads();
    }
    if (t == 0) {
        out[0] = rc[0] * (1.0f / 256.0f);   // CLS_W = 1.0
        out[1] = rr[0] * (1.0f / 256.0f);
    }
}

extern "C" void kernel_launch(void* const* d_in, const int* in_sizes, int n_in,
                              void* d_out, int out_size) {
    const float2* score   = (const float2*)d_in[0];   // [N,2]
    const float4* pred    = (const float4*)d_in[1];   // [N,4]
    const float4* anchors = (const float4*)d_in[2];   // [N,4]
    const float4* gt      = (const float4*)d_in[3];   // [M,4]
    float* out = (float*)d_out;

    int N = in_sizes[2] / 4;
    int M = in_sizes[3] / 4;

    k_front<<<FBLK, FTHR>>>(anchors, gt, N, M);
    if (N > FRONT) {
        int nb = (N - FRONT + 255) / 256;
        k_full<<<nb, 256>>>(anchors, gt, N, M);
    }
    k_tail<<<1, 256>>>(score, pred, anchors, gt, out, N, M);
}

// round 4
// speedup vs baseline: 3.3405x; 1.1552x over previous
#include <cuda_runtime.h>
#include <cuda_bf16.h>

// ---------------------------------------------------------------------------
// RPN training loss (faithful port of the buggy reference):
//   gt_idx[i] = argmax_j IoU(anchor_i, gt_j)   (first-max wins ties)
//   label = 1 if gt_idx >= 1, 0 if gt_idx == 0  (every anchor is pos or neg)
//   sel   = first min(num_pos,128) positives by anchor index, then negatives
//           by anchor index (spilling back into positives if negatives run out)
//   cls   = mean softmax-CE over 256 samples
//   reg   = mean over 256 of 2 * sum smoothL1(label * (pred - encode))
//
// Only the earliest anchors matter: selection is decided once 128 positives
// AND 128 negatives have been seen (in index order). With this data's rates
// (~0.89 pos / ~0.11 neg) that happens within ~1200 anchors.
//   k_front<<<128,32>>> : exact argmax for anchors [0, 4096) + per-warp counts
//   k_tail <<<1,256>>>  : reduce counts; if front insufficient, compute the
//                         rest in-block (exact fallback); ordered scan to
//                         collect first pos/neg lists; compute both losses.
// Argmax is division-free: best kept as a rational (bestI/bestU), update when
// inter*bestU > bestI*uni (strict '>' => first-max wins, matching jnp.argmax).
// ILP-2: independent even-j / odd-j chains merged at the end (chain0 = even
// indices wins merge ties).
// ---------------------------------------------------------------------------

#define NMAX     (1 << 20)
#define FBLK     128
#define FTHR     32
#define FRONT    (FBLK * FTHR)    // 4096
#define SMG      1024             // gt boxes cached in smem (M <= SMG)
#define CAP      256

__device__ int g_gt_idx[NMAX];
__device__ int g_fp[FBLK];
__device__ int g_fn[FBLK];

// ---- division-free argmax, ILP-2 (even/odd chains) -----------------------
__device__ __forceinline__ int argmax_iou2(const float4 a,
                                           const float4* __restrict__ gtp,
                                           const float* __restrict__ areap,
                                           int M) {
    float areaA = (a.z - a.x) * (a.w - a.y);
    float bI0 = 0.0f, bU0 = 1.0f;   int b0 = 0;
    float bI1 = 0.0f, bU1 = 1.0f;   int b1 = 0;
    int j = 0;
    #pragma unroll 2
    for (; j + 1 < M; j += 2) {
        {
            float4 g = gtp[j];
            float w = fmaxf(fminf(a.z, g.z) - fmaxf(a.x, g.x), 0.0f);
            float h = fmaxf(fminf(a.w, g.w) - fmaxf(a.y, g.y), 0.0f);
            float inter = w * h;
            float uni = (areaA + areap[j]) - inter;
            bool u = inter * bU0 > bI0 * uni;
            bI0 = u ? inter : bI0;  bU0 = u ? uni : bU0;  b0 = u ? j : b0;
        }
        {
            float4 g = gtp[j + 1];
            float w = fmaxf(fminf(a.z, g.z) - fmaxf(a.x, g.x), 0.0f);
            float h = fmaxf(fminf(a.w, g.w) - fmaxf(a.y, g.y), 0.0f);
            float inter = w * h;
            float uni = (areaA + areap[j + 1]) - inter;
            bool u = inter * bU1 > bI1 * uni;
            bI1 = u ? inter : bI1;  bU1 = u ? uni : bU1;  b1 = u ? (j + 1) : b1;
        }
    }
    if (j < M) {  // M odd: last (even) index -> chain0
        float4 g = gtp[j];
        float w = fmaxf(fminf(a.z, g.z) - fmaxf(a.x, g.x), 0.0f);
        float h = fmaxf(fminf(a.w, g.w) - fmaxf(a.y, g.y), 0.0f);
        float inter = w * h;
        float uni = (areaA + areap[j]) - inter;
        bool u = inter * bU0 > bI0 * uni;
        bI0 = u ? inter : bI0;  bU0 = u ? uni : bU0;  b0 = u ? j : b0;
    }
    // merge: chain1 only on strict win (ties -> chain0, the even/first chain)
    return (bI1 * bU0 > bI0 * bU1) ? b1 : b0;
}

// --------------------------------------------------------------------------
// K1: argmax for anchors [0, FRONT) + per-warp pos/neg counts.
// --------------------------------------------------------------------------
__global__ void k_front(const float4* __restrict__ anchors,
                        const float4* __restrict__ gt,
                        int N, int M) {
    __shared__ float4 sg[SMG];
    __shared__ float  sga[SMG];
    int Ms = min(M, SMG);
    for (int j = threadIdx.x; j < Ms; j += FTHR) {
        float4 g = gt[j];
        sg[j]  = g;
        sga[j] = (g.z - g.x) * (g.w - g.y);
    }
    __syncwarp();

    int i = blockIdx.x * FTHR + threadIdx.x;
    int best = 0;
    bool valid = (i < N);
    if (valid) {
        if (M <= SMG) {
            best = argmax_iou2(anchors[i], sg, sga, M);
        } else {
            // huge-M fallback: stream gt from global (exact, slow)
            float4 a = anchors[i];
            float areaA = (a.z - a.x) * (a.w - a.y);
            float bI = 0.0f, bU = 1.0f;
            for (int j = 0; j < M; ++j) {
                float4 g = __ldg(&gt[j]);
                float areaB = (g.z - g.x) * (g.w - g.y);
                float w = fmaxf(fminf(a.z, g.z) - fmaxf(a.x, g.x), 0.0f);
                float h = fmaxf(fminf(a.w, g.w) - fmaxf(a.y, g.y), 0.0f);
                float inter = w * h;
                float uni = (areaA + areaB) - inter;
                bool u = inter * bU > bI * uni;
                bI = u ? inter : bI;  bU = u ? uni : bU;  best = u ? j : best;
            }
        }
        g_gt_idx[i] = best;
    }

    unsigned bp = __ballot_sync(0xffffffffu, valid && best >= 1);
    unsigned bn = __ballot_sync(0xffffffffu, valid && best == 0);
    if (threadIdx.x == 0) {
        g_fp[blockIdx.x] = __popc(bp);
        g_fn[blockIdx.x] = __popc(bn);
    }
}

// --------------------------------------------------------------------------
// K2: one block, 256 threads. Sufficiency -> (rare) fallback -> ordered
// select of first pos/neg anchors -> 256-sample loss.
// --------------------------------------------------------------------------
__global__ void k_tail(const float2* __restrict__ score,
                       const float4* __restrict__ pred,
                       const float4* __restrict__ anchors,
                       const float4* __restrict__ gt,
                       float* __restrict__ out,
                       int N, int M) {
    __shared__ float4 sg[SMG];
    __shared__ float  sga[SMG];
    __shared__ int s_pos[CAP], s_neg[CAP];
    __shared__ int wp[8], wn[8];
    __shared__ int redp[256], redn[256];
    __shared__ int s_cntp, s_cntn;
    __shared__ float rc[256], rr[256];

    int t = threadIdx.x;
    int lane = t & 31;
    int warp = t >> 5;
    unsigned ltmask = (1u << lane) - 1u;

    s_pos[t] = 0;
    s_neg[t] = 0;

    // cache gt (needed for loss encode; also for fallback argmax)
    int Ms = min(M, SMG);
    for (int j = t; j < Ms; j += 256) {
        float4 g = gt[j];
        sg[j]  = g;
        sga[j] = (g.z - g.x) * (g.w - g.y);
    }

    // reduce front counts
    redp[t] = (t < FBLK) ? g_fp[t] : 0;
    redn[t] = (t < FBLK) ? g_fn[t] : 0;
    __syncthreads();
    for (int off = 128; off > 0; off >>= 1) {
        if (t < off) { redp[t] += redp[t + off]; redn[t] += redn[t + off]; }
        __syncthreads();
    }
    bool suff = (redp[0] >= 128) && (redn[0] >= 128);
    int limit = suff ? min(FRONT, N) : N;

    // exact fallback: front region lacked 128 pos or 128 neg -> finish
    // gt_idx for [FRONT, N) in-block (essentially never taken).
    if (!suff && N > FRONT) {
        for (int i = FRONT + t; i < N; i += 256) {
            int best;
            if (M <= SMG) {
                best = argmax_iou2(anchors[i], sg, sga, M);
            } else {
                float4 a = anchors[i];
                float areaA = (a.z - a.x) * (a.w - a.y);
                float bI = 0.0f, bU = 1.0f;
                best = 0;
                for (int j = 0; j < M; ++j) {
                    float4 g = __ldg(&gt[j]);
                    float areaB = (g.z - g.x) * (g.w - g.y);
                    float w = fmaxf(fminf(a.z, g.z) - fmaxf(a.x, g.x), 0.0f);
                    float h = fmaxf(fminf(a.w, g.w) - fmaxf(a.y, g.y), 0.0f);
                    float inter = w * h;
                    float uni = (areaA + areaB) - inter;
                    bool u = inter * bU > bI * uni;
                    bI = u ? inter : bI;  bU = u ? uni : bU;  best = u ? j : best;
                }
            }
            g_gt_idx[i] = best;
        }
        __syncthreads();
    }

    if (t == 0) { s_cntp = 0; s_cntn = 0; }
    __syncthreads();

    // ordered chunk scan (double-buffered). Stop once >=128 pos AND >=128 neg:
    // then cur_pos=128, no spill, and only the first 128 of each list is read.
    int gi0 = (t < limit) ? g_gt_idx[t] : -1;
    for (int base = 0; base < limit; base += 256) {
        int idx1 = base + 256 + t;
        int gi1 = (idx1 < limit) ? g_gt_idx[idx1] : -1;

        int cp0 = s_cntp, cn0 = s_cntn;
        int is_pos = (gi0 >= 1);
        int is_neg = (gi0 == 0);
        unsigned bp = __ballot_sync(0xffffffffu, is_pos);
        unsigned bn = __ballot_sync(0xffffffffu, is_neg);
        if (lane == 0) { wp[warp] = __popc(bp); wn[warp] = __popc(bn); }
        __syncthreads();
        int basep = 0, basen = 0;
        for (int w = 0; w < warp; ++w) { basep += wp[w]; basen += wn[w]; }
        if (is_pos) {
            int r = cp0 + basep + __popc(bp & ltmask);
            if (r < CAP) s_pos[r] = base + t;
        }
        if (is_neg) {
            int r = cn0 + basen + __popc(bn & ltmask);
            if (r < CAP) s_neg[r] = base + t;
        }
        if (t == 0) {
            int tp = 0, tn = 0;
            #pragma unroll
            for (int w = 0; w < 8; ++w) { tp += wp[w]; tn += wn[w]; }
            s_cntp = cp0 + tp;
            s_cntn = cn0 + tn;
        }
        __syncthreads();
        if (s_cntp >= 128 && s_cntn >= 128) break;
        gi0 = gi1;
    }

    // mapping (counts >=128 after early stop give identical results to true
    // totals: cur_pos=128 and every j<128 satisfies j<num_neg)
    int num_pos = s_cntp;
    int num_neg = s_cntn;
    int cur_pos = min(num_pos, 128);

    int a, label;
    if (t < cur_pos) {
        a = s_pos[t];
        label = 1;
    } else {
        int j = t - cur_pos;
        if (j < num_neg) {
            a = s_neg[min(j, CAP - 1)];
            label = 0;
        } else {
            // stable neg_order spills into positives in anchor-index order
            a = s_pos[min(j - num_neg, CAP - 1)];
            label = 1;
        }
    }

    // classification: -log_softmax(score[a])[label]
    float2 s = score[a];
    float m = fmaxf(s.x, s.y);
    float lse = m + logf(expf(s.x - m) + expf(s.y - m));
    float cls = lse - (label ? s.y : s.x);

    // regression: smooth-L1 on encoded target, zeroed for negatives
    float4 ab = anchors[a];
    int gi = g_gt_idx[a];
    float4 gb = (gi < Ms) ? sg[gi] : gt[gi];
    float aw = ab.z - ab.x, ah = ab.w - ab.y;
    float acx = ab.x + 0.5f * aw, acy = ab.y + 0.5f * ah;
    float gw = gb.z - gb.x, gh = gb.w - gb.y;
    float gcx = gb.x + 0.5f * gw, gcy = gb.y + 0.5f * gh;
    float t0 = (gcx - acx) / aw;
    float t1 = (gcy - acy) / ah;
    float t2 = logf(gw / aw);
    float t3 = logf(gh / ah);
    float4 p = pred[a];
    float fl = (float)label;
    float d0 = fl * (p.x - t0);
    float d1 = fl * (p.y - t1);
    float d2 = fl * (p.z - t2);
    float d3 = fl * (p.w - t3);
    float ad0 = fabsf(d0), ad1 = fabsf(d1), ad2 = fabsf(d2), ad3 = fabsf(d3);
    float s0 = (ad0 < 1.0f) ? 0.5f * d0 * d0 : ad0 - 0.5f;
    float s1 = (ad1 < 1.0f) ? 0.5f * d1 * d1 : ad1 - 0.5f;
    float s2 = (ad2 < 1.0f) ? 0.5f * d2 * d2 : ad2 - 0.5f;
    float s3 = (ad3 < 1.0f) ? 0.5f * d3 * d3 : ad3 - 0.5f;
    float reg = 2.0f * (s0 + s1 + s2 + s3);

    rc[t] = cls;
    rr[t] = reg;
    __syncthreads();
    for (int off = 128; off > 0; off >>= 1) {
        if (t < off) { rc[t] += rc[t + off]; rr[t] += rr[t + off]; }
        __syncthreads();
    }
    if (t == 0) {
        out[0] = rc[0] * (1.0f / 256.0f);   // CLS_W = 1.0
        out[1] = rr[0] * (1.0f / 256.0f);
    }
}

extern "C" void kernel_launch(void* const* d_in, const int* in_sizes, int n_in,
                              void* d_out, int out_size) {
    const float2* score   = (const float2*)d_in[0];   // [N,2]
    const float4* pred    = (const float4*)d_in[1];   // [N,4]
    const float4* anchors = (const float4*)d_in[2];   // [N,4]
    const float4* gt      = (const float4*)d_in[3];   // [M,4]
    float* out = (float*)d_out;

    int N = in_sizes[2] / 4;
    int M = in_sizes[3] / 4;

    k_front<<<FBLK, FTHR>>>(anchors, gt, N, M);
    k_tail<<<1, 256>>>(score, pred, anchors, gt, out, N, M);
}